// round 1
// baseline (speedup 1.0000x reference)
#include <cuda_runtime.h>
#include <math.h>

// Problem constants
#define BB   8
#define CC   128
#define HH   64
#define WW   64
#define HW   4096           // 64*64
#define OCC  18             // offset conv output channels
#define KK9  9
#define CIKK 1152           // 128*9
#define DT   8              // pixels per deform block

// ---------------- device scratch (no allocations allowed) ----------------
__device__ float g_off1[BB * OCC * HW];
__device__ float g_off2[BB * OCC * HW];
__device__ float g_out1[BB * CC * HW];
__device__ float g_xt  [BB * HW * CC];   // NHWC staging

// ---------------- offset conv: 3x3, pad 1, stride 1, Cout=18 ----------------
// One block per (b, h) row. Block (64, 6): tx = w, ty owns 3 output channels.
// x and weights staged through shared in 16-channel chunks.
__global__ __launch_bounds__(384) void offconv_kernel(
    const float* __restrict__ x, const float* __restrict__ wt,
    const float* __restrict__ bias, float* __restrict__ out)
{
    int bh = blockIdx.x;
    int b = bh >> 6;
    int h = bh & 63;
    int tx = threadIdx.x;           // 0..63 (w)
    int ty = threadIdx.y;           // 0..5
    int tid = ty * 64 + tx;         // 0..383

    __shared__ float xs[3][16][66];     // [ky][ci][w+1 halo]
    __shared__ float ws[16][18][12];    // [ci][oc][kk padded to 12 for v4]

    float acc[3] = {0.f, 0.f, 0.f};
    const float* xb = x + b * CC * HW;

    for (int c0 = 0; c0 < CC; c0 += 16) {
        __syncthreads();
        // stage x rows h-1..h+1 with 1-pixel halo, zero padded
        for (int i = tid; i < 3 * 16 * 66; i += 384) {
            int ky = i / (16 * 66);
            int r  = i % (16 * 66);
            int ci = r / 66;
            int wp = r % 66;
            int iy = h + ky - 1;
            int ix = wp - 1;
            float v = 0.f;
            if (iy >= 0 && iy < HH && ix >= 0 && ix < WW)
                v = xb[(c0 + ci) * HW + iy * WW + ix];
            xs[ky][ci][wp] = v;
        }
        // stage weights
        for (int i = tid; i < 16 * 18 * 9; i += 384) {
            int ci = i / 162;
            int r  = i % 162;
            int oc = r / 9;
            int kk = r % 9;
            ws[ci][oc][kk] = wt[oc * CIKK + (c0 + ci) * 9 + kk];
        }
        __syncthreads();

        for (int ci = 0; ci < 16; ci++) {
            float xr[9];
            #pragma unroll
            for (int ky = 0; ky < 3; ky++)
                #pragma unroll
                for (int kx = 0; kx < 3; kx++)
                    xr[ky * 3 + kx] = xs[ky][ci][tx + kx];
            #pragma unroll
            for (int j = 0; j < 3; j++) {
                int oc = ty * 3 + j;
                const float4* wp4 = (const float4*)&ws[ci][oc][0];
                float4 wa = wp4[0];
                float4 wb = wp4[1];
                float  w8 = ws[ci][oc][8];
                acc[j] += wa.x * xr[0] + wa.y * xr[1] + wa.z * xr[2]
                        + wa.w * xr[3] + wb.x * xr[4] + wb.y * xr[5]
                        + wb.z * xr[6] + wb.w * xr[7] + w8 * xr[8];
            }
        }
    }

    #pragma unroll
    for (int j = 0; j < 3; j++) {
        int oc = ty * 3 + j;
        out[((b * OCC + oc) << 12) + h * WW + tx] = acc[j] + bias[oc];
    }
}

// ---------------- NCHW -> NHWC transpose (per batch: [128][4096] -> [4096][128]) ----------------
__global__ void transpose_kernel(const float* __restrict__ in, float* __restrict__ out)
{
    __shared__ float tile[32][33];
    int b  = blockIdx.z;
    int c0 = blockIdx.y * 32;
    int p0 = blockIdx.x * 32;
    int tx = threadIdx.x, ty = threadIdx.y;   // (32, 8)
    const float* ib = in + b * CC * HW;
    float* ob = out + b * HW * CC;
    #pragma unroll
    for (int k = 0; k < 4; k++) {
        int c = c0 + ty + k * 8;
        tile[ty + k * 8][tx] = ib[c * HW + p0 + tx];
    }
    __syncthreads();
    #pragma unroll
    for (int k = 0; k < 4; k++) {
        int p = p0 + ty + k * 8;
        ob[p * CC + c0 + tx] = tile[tx][ty + k * 8];
    }
}

// ---------------- deform conv (3x3, pad 2, dil 2) + BN (+ residual) + ReLU ----------------
// Block: 128 threads, DT=8 pixels. Phase 1: bilinear gather into smem im2col
// tile [cik=ci*9+kk][t]. Phase 2: thread co does flattened 1152-dot over DT pixels.
__global__ __launch_bounds__(128) void deform_kernel(
    const float* __restrict__ xt,      // NHWC input
    const float* __restrict__ off,     // [b][18][hw]
    const float* __restrict__ wdc,     // [co][ci][3][3]
    const float* __restrict__ gamma, const float* __restrict__ beta,
    const float* __restrict__ mean,  const float* __restrict__ var,
    const float* __restrict__ resid,   // nullptr for stage 1
    float* __restrict__ out)           // NCHW
{
    int bx   = blockIdx.x;
    int b    = bx >> 9;                // 512 blocks per batch
    int pix0 = (bx & 511) << 3;
    int tid  = threadIdx.x;

    __shared__ float s_samp[CIKK * DT];      // 36 KB
    __shared__ int   s_y0[DT * KK9], s_x0[DT * KK9];
    __shared__ float s_fy[DT * KK9], s_fx[DT * KK9];

    // sampling coordinates (72 of them)
    if (tid < DT * KK9) {
        int t  = tid / KK9;
        int kk = tid % KK9;
        int pix = pix0 + t;
        int h = pix >> 6;
        int w = pix & 63;
        int ky = kk / 3, kx = kk % 3;
        const float* ob = off + b * OCC * HW;
        float dy = ob[(2 * kk)     * HW + pix];
        float dx = ob[(2 * kk + 1) * HW + pix];
        float ys = (float)(h - 2 + 2 * ky) + dy;
        float xs = (float)(w - 2 + 2 * kx) + dx;
        float y0f = floorf(ys), x0f = floorf(xs);
        s_y0[tid] = (int)y0f;
        s_x0[tid] = (int)x0f;
        s_fy[tid] = ys - y0f;
        s_fx[tid] = xs - x0f;
    }
    __syncthreads();

    // gather: thread = channel ci, coalesced NHWC reads
    {
        const float* xb = xt + b * HW * CC;
        int ci = tid;
        for (int i = 0; i < DT * KK9; i++) {
            int   y0 = s_y0[i], x0 = s_x0[i];
            float fy = s_fy[i], fx = s_fx[i];
            int y1 = y0 + 1, x1 = x0 + 1;
            bool y0ok = (y0 >= 0) && (y0 < HH);
            bool y1ok = (y1 >= 0) && (y1 < HH);
            bool x0ok = (x0 >= 0) && (x0 < WW);
            bool x1ok = (x1 >= 0) && (x1 < WW);
            float v00 = (y0ok && x0ok) ? xb[(y0 * WW + x0) * CC + ci] : 0.f;
            float v01 = (y0ok && x1ok) ? xb[(y0 * WW + x1) * CC + ci] : 0.f;
            float v10 = (y1ok && x0ok) ? xb[(y1 * WW + x0) * CC + ci] : 0.f;
            float v11 = (y1ok && x1ok) ? xb[(y1 * WW + x1) * CC + ci] : 0.f;
            float s = (1.f - fy) * ((1.f - fx) * v00 + fx * v01)
                    +        fy  * ((1.f - fx) * v10 + fx * v11);
            int t  = i / KK9;
            int kk = i - t * KK9;
            s_samp[(ci * KK9 + kk) * DT + t] = s;
        }
    }
    __syncthreads();

    // compute: thread = output channel co; flattened cik loop matches weight layout
    int co = tid;
    float acc[DT];
    #pragma unroll
    for (int t = 0; t < DT; t++) acc[t] = 0.f;

    const float* wrow = wdc + co * CIKK;     // 1152 contiguous, 16B aligned per row
    #pragma unroll 2
    for (int cik = 0; cik < CIKK; cik += 4) {
        float4 wq = *(const float4*)(wrow + cik);
        #pragma unroll
        for (int u = 0; u < 4; u++) {
            float wv = (u == 0) ? wq.x : (u == 1) ? wq.y : (u == 2) ? wq.z : wq.w;
            const float4* sp = (const float4*)&s_samp[(cik + u) * DT];
            float4 a = sp[0];
            float4 c = sp[1];
            acc[0] += wv * a.x; acc[1] += wv * a.y;
            acc[2] += wv * a.z; acc[3] += wv * a.w;
            acc[4] += wv * c.x; acc[5] += wv * c.y;
            acc[6] += wv * c.z; acc[7] += wv * c.w;
        }
    }

    // BN (+residual) + ReLU, NCHW output
    float inv = gamma[co] * rsqrtf(var[co] + 1e-5f);
    float add = beta[co] - mean[co] * inv;
    int base = ((b * CC + co) << 12) + pix0;
    #pragma unroll
    for (int t = 0; t < DT; t++) {
        float val = acc[t] * inv + add;
        if (resid) val += resid[base + t];
        out[base + t] = fmaxf(val, 0.f);
    }
}

// ---------------- launch ----------------
extern "C" void kernel_launch(void* const* d_in, const int* in_sizes, int n_in,
                              void* d_out, int out_size)
{
    const float* x      = (const float*)d_in[0];
    const float* w_off1 = (const float*)d_in[1];
    const float* b_off1 = (const float*)d_in[2];
    const float* w_dc1  = (const float*)d_in[3];
    const float* g1     = (const float*)d_in[4];
    const float* beta1  = (const float*)d_in[5];
    const float* m1     = (const float*)d_in[6];
    const float* v1     = (const float*)d_in[7];
    const float* w_off2 = (const float*)d_in[8];
    const float* b_off2 = (const float*)d_in[9];
    const float* w_dc2  = (const float*)d_in[10];
    const float* g2     = (const float*)d_in[11];
    const float* beta2  = (const float*)d_in[12];
    const float* m2     = (const float*)d_in[13];
    const float* v2     = (const float*)d_in[14];
    float* out = (float*)d_out;

    float *off1, *off2, *out1, *xt;
    cudaGetSymbolAddress((void**)&off1, g_off1);
    cudaGetSymbolAddress((void**)&off2, g_off2);
    cudaGetSymbolAddress((void**)&out1, g_out1);
    cudaGetSymbolAddress((void**)&xt,   g_xt);

    dim3 ocBlk(64, 6);
    dim3 trGrid(HW / 32, CC / 32, BB), trBlk(32, 8);

    // stage 1
    offconv_kernel<<<BB * HH, ocBlk>>>(x, w_off1, b_off1, off1);
    transpose_kernel<<<trGrid, trBlk>>>(x, xt);
    deform_kernel<<<BB * HW / DT, 128>>>(xt, off1, w_dc1, g1, beta1, m1, v1,
                                         nullptr, out1);
    // stage 2
    offconv_kernel<<<BB * HH, ocBlk>>>(out1, w_off2, b_off2, off2);
    transpose_kernel<<<trGrid, trBlk>>>(out1, xt);
    deform_kernel<<<BB * HW / DT, 128>>>(xt, off2, w_dc2, g2, beta2, m2, v2,
                                         x, out);
}

// round 2
// speedup vs baseline: 1.9635x; 1.9635x over previous
#include <cuda_runtime.h>
#include <math.h>

// Problem constants
#define BB   8
#define CC   128
#define HH   64
#define WW   64
#define HW   4096           // 64*64
#define OCC  18             // offset conv output channels
#define KK9  9
#define CIKK 1152           // 128*9
#define DT   8              // pixels per deform block
#define CISTR 76            // padded per-ci stride in sample tile (floats)

// ---------------- device scratch (no allocations allowed) ----------------
__device__ float g_off1[BB * OCC * HW];
__device__ float g_off2[BB * OCC * HW];
__device__ float g_out1[BB * CC * HW];
__device__ float g_xt  [BB * HW * CC];     // NHWC staging
__device__ float g_wt1 [CIKK * CC];        // transposed deform weights [cik][co]
__device__ float g_wt2 [CIKK * CC];

// ---------------- weight transpose prep: [co][cik] -> [cik][co] ----------------
__global__ void wtrans_kernel(const float* __restrict__ w1,
                              const float* __restrict__ w2)
{
    int cik = blockIdx.x;      // 0..1151
    int co  = threadIdx.x;     // 0..127
    g_wt1[cik * CC + co] = w1[co * CIKK + cik];
    g_wt2[cik * CC + co] = w2[co * CIKK + cik];
}

// ---------------- offset conv: 3x3, pad 1, stride 1, Cout=18 ----------------
__global__ __launch_bounds__(384) void offconv_kernel(
    const float* __restrict__ x, const float* __restrict__ wt,
    const float* __restrict__ bias, float* __restrict__ out)
{
    int bh = blockIdx.x;
    int b = bh >> 6;
    int h = bh & 63;
    int tx = threadIdx.x;           // 0..63 (w)
    int ty = threadIdx.y;           // 0..5
    int tid = ty * 64 + tx;         // 0..383

    __shared__ float xs[3][16][66];     // [ky][ci][w+1 halo]
    __shared__ float ws[16][18][12];    // [ci][oc][kk padded to 12 for v4]

    float acc[3] = {0.f, 0.f, 0.f};
    const float* xb = x + b * CC * HW;

    for (int c0 = 0; c0 < CC; c0 += 16) {
        __syncthreads();
        for (int i = tid; i < 3 * 16 * 66; i += 384) {
            int ky = i / (16 * 66);
            int r  = i % (16 * 66);
            int ci = r / 66;
            int wp = r % 66;
            int iy = h + ky - 1;
            int ix = wp - 1;
            float v = 0.f;
            if (iy >= 0 && iy < HH && ix >= 0 && ix < WW)
                v = xb[(c0 + ci) * HW + iy * WW + ix];
            xs[ky][ci][wp] = v;
        }
        for (int i = tid; i < 16 * 18 * 9; i += 384) {
            int ci = i / 162;
            int r  = i % 162;
            int oc = r / 9;
            int kk = r % 9;
            ws[ci][oc][kk] = wt[oc * CIKK + (c0 + ci) * 9 + kk];
        }
        __syncthreads();

        for (int ci = 0; ci < 16; ci++) {
            float xr[9];
            #pragma unroll
            for (int ky = 0; ky < 3; ky++)
                #pragma unroll
                for (int kx = 0; kx < 3; kx++)
                    xr[ky * 3 + kx] = xs[ky][ci][tx + kx];
            #pragma unroll
            for (int j = 0; j < 3; j++) {
                int oc = ty * 3 + j;
                const float4* wp4 = (const float4*)&ws[ci][oc][0];
                float4 wa = wp4[0];
                float4 wb = wp4[1];
                float  w8 = ws[ci][oc][8];
                acc[j] += wa.x * xr[0] + wa.y * xr[1] + wa.z * xr[2]
                        + wa.w * xr[3] + wb.x * xr[4] + wb.y * xr[5]
                        + wb.z * xr[6] + wb.w * xr[7] + w8 * xr[8];
            }
        }
    }

    #pragma unroll
    for (int j = 0; j < 3; j++) {
        int oc = ty * 3 + j;
        out[((b * OCC + oc) << 12) + h * WW + tx] = acc[j] + bias[oc];
    }
}

// ---------------- NCHW -> NHWC transpose ----------------
__global__ void transpose_kernel(const float* __restrict__ in, float* __restrict__ out)
{
    __shared__ float tile[32][33];
    int b  = blockIdx.z;
    int c0 = blockIdx.y * 32;
    int p0 = blockIdx.x * 32;
    int tx = threadIdx.x, ty = threadIdx.y;   // (32, 8)
    const float* ib = in + b * CC * HW;
    float* ob = out + b * HW * CC;
    #pragma unroll
    for (int k = 0; k < 4; k++) {
        int c = c0 + ty + k * 8;
        tile[ty + k * 8][tx] = ib[c * HW + p0 + tx];
    }
    __syncthreads();
    #pragma unroll
    for (int k = 0; k < 4; k++) {
        int p = p0 + ty + k * 8;
        ob[p * CC + c0 + tx] = tile[tx][ty + k * 8];
    }
}

// ---------------- deform conv (3x3, pad 2, dil 2) + BN (+ residual) + ReLU --
// 64-thread block, DT=8 pixels. Thread t computes co = 2t, 2t+1.
// Weights pre-transposed to [cik][co] so warp weight loads are coalesced LDG.64.
__global__ __launch_bounds__(64) void deform_kernel(
    const float* __restrict__ xt,      // NHWC input
    const float* __restrict__ off,     // [b][18][hw]
    const float* __restrict__ wtt,     // transposed weights [cik][co]
    const float* __restrict__ gamma, const float* __restrict__ beta,
    const float* __restrict__ mean,  const float* __restrict__ var,
    const float* __restrict__ resid,   // nullptr for stage 1
    float* __restrict__ out)           // NCHW
{
    int bx   = blockIdx.x;
    int b    = bx >> 9;                // 512 blocks per batch
    int pix0 = (bx & 511) << 3;
    int tid  = threadIdx.x;            // 0..63

    __shared__ float s_samp[CC * CISTR];     // 128 * 76 * 4 = 38912 B
    __shared__ int   s_y0[72], s_x0[72];
    __shared__ float s_fy[72], s_fx[72];

    // sampling coordinates: j = kk*8 + t
    for (int j = tid; j < 72; j += 64) {
        int kk = j >> 3;
        int t  = j & 7;
        int pix = pix0 + t;
        int h = pix >> 6;
        int w = pix & 63;
        int ky = kk / 3, kx = kk % 3;
        const float* ob = off + b * OCC * HW;
        float dy = ob[(2 * kk)     * HW + pix];
        float dx = ob[(2 * kk + 1) * HW + pix];
        float ys = (float)(h - 2 + 2 * ky) + dy;
        float xs = (float)(w - 2 + 2 * kx) + dx;
        float y0f = floorf(ys), x0f = floorf(xs);
        s_y0[j] = (int)y0f;
        s_x0[j] = (int)x0f;
        s_fy[j] = ys - y0f;
        s_fx[j] = xs - x0f;
    }
    __syncthreads();

    // gather: lanes = consecutive ci -> coalesced 128B NHWC reads
    {
        const float* xb = xt + b * HW * CC;
        for (int j = 0; j < 72; j++) {
            int   y0 = s_y0[j], x0 = s_x0[j];
            float fy = s_fy[j], fx = s_fx[j];
            int y1 = y0 + 1, x1 = x0 + 1;
            bool y0ok = (y0 >= 0) && (y0 < HH);
            bool y1ok = (y1 >= 0) && (y1 < HH);
            bool x0ok = (x0 >= 0) && (x0 < WW);
            bool x1ok = (x1 >= 0) && (x1 < WW);
            int o00 = (y0 * WW + x0) * CC;
            int o01 = (y0 * WW + x1) * CC;
            int o10 = (y1 * WW + x0) * CC;
            int o11 = (y1 * WW + x1) * CC;
            float wa = (1.f - fy) * (1.f - fx);
            float wb = (1.f - fy) * fx;
            float wc = fy * (1.f - fx);
            float wd = fy * fx;
            #pragma unroll
            for (int half = 0; half < 2; half++) {
                int ci = tid + half * 64;
                float v00 = (y0ok && x0ok) ? xb[o00 + ci] : 0.f;
                float v01 = (y0ok && x1ok) ? xb[o01 + ci] : 0.f;
                float v10 = (y1ok && x0ok) ? xb[o10 + ci] : 0.f;
                float v11 = (y1ok && x1ok) ? xb[o11 + ci] : 0.f;
                s_samp[ci * CISTR + j] = wa * v00 + wb * v01 + wc * v10 + wd * v11;
            }
        }
    }
    __syncthreads();

    // compute: thread t handles co0 = 2t, co1 = 2t+1 over 8 pixels
    float acc0[DT], acc1[DT];
    #pragma unroll
    for (int t = 0; t < DT; t++) { acc0[t] = 0.f; acc1[t] = 0.f; }

    const float* wp = wtt + 2 * tid;       // advance by CC per cik
    for (int ci = 0; ci < CC; ci++) {
        const float* srow = &s_samp[ci * CISTR];
        #pragma unroll
        for (int kk = 0; kk < KK9; kk++) {
            float2 w2 = *(const float2*)wp;
            wp += CC;
            float4 a = *(const float4*)(srow + kk * 8);
            float4 c = *(const float4*)(srow + kk * 8 + 4);
            acc0[0] = fmaf(w2.x, a.x, acc0[0]);
            acc0[1] = fmaf(w2.x, a.y, acc0[1]);
            acc0[2] = fmaf(w2.x, a.z, acc0[2]);
            acc0[3] = fmaf(w2.x, a.w, acc0[3]);
            acc0[4] = fmaf(w2.x, c.x, acc0[4]);
            acc0[5] = fmaf(w2.x, c.y, acc0[5]);
            acc0[6] = fmaf(w2.x, c.z, acc0[6]);
            acc0[7] = fmaf(w2.x, c.w, acc0[7]);
            acc1[0] = fmaf(w2.y, a.x, acc1[0]);
            acc1[1] = fmaf(w2.y, a.y, acc1[1]);
            acc1[2] = fmaf(w2.y, a.z, acc1[2]);
            acc1[3] = fmaf(w2.y, a.w, acc1[3]);
            acc1[4] = fmaf(w2.y, c.x, acc1[4]);
            acc1[5] = fmaf(w2.y, c.y, acc1[5]);
            acc1[6] = fmaf(w2.y, c.z, acc1[6]);
            acc1[7] = fmaf(w2.y, c.w, acc1[7]);
        }
    }

    // BN (+residual) + ReLU, NCHW output, vectorized stores
    #pragma unroll
    for (int c = 0; c < 2; c++) {
        int co = 2 * tid + c;
        float* accp = c ? acc1 : acc0;
        float inv = gamma[co] * rsqrtf(var[co] + 1e-5f);
        float add = beta[co] - mean[co] * inv;
        int base = ((b * CC + co) << 12) + pix0;
        float4 r0, r1;
        r0.x = accp[0] * inv + add;  r0.y = accp[1] * inv + add;
        r0.z = accp[2] * inv + add;  r0.w = accp[3] * inv + add;
        r1.x = accp[4] * inv + add;  r1.y = accp[5] * inv + add;
        r1.z = accp[6] * inv + add;  r1.w = accp[7] * inv + add;
        if (resid) {
            const float4* rp = (const float4*)(resid + base);
            float4 q0 = rp[0], q1 = rp[1];
            r0.x += q0.x; r0.y += q0.y; r0.z += q0.z; r0.w += q0.w;
            r1.x += q1.x; r1.y += q1.y; r1.z += q1.z; r1.w += q1.w;
        }
        r0.x = fmaxf(r0.x, 0.f); r0.y = fmaxf(r0.y, 0.f);
        r0.z = fmaxf(r0.z, 0.f); r0.w = fmaxf(r0.w, 0.f);
        r1.x = fmaxf(r1.x, 0.f); r1.y = fmaxf(r1.y, 0.f);
        r1.z = fmaxf(r1.z, 0.f); r1.w = fmaxf(r1.w, 0.f);
        *(float4*)(out + base)     = r0;
        *(float4*)(out + base + 4) = r1;
    }
}

// ---------------- launch ----------------
extern "C" void kernel_launch(void* const* d_in, const int* in_sizes, int n_in,
                              void* d_out, int out_size)
{
    const float* x      = (const float*)d_in[0];
    const float* w_off1 = (const float*)d_in[1];
    const float* b_off1 = (const float*)d_in[2];
    const float* w_dc1  = (const float*)d_in[3];
    const float* g1     = (const float*)d_in[4];
    const float* beta1  = (const float*)d_in[5];
    const float* m1     = (const float*)d_in[6];
    const float* v1     = (const float*)d_in[7];
    const float* w_off2 = (const float*)d_in[8];
    const float* b_off2 = (const float*)d_in[9];
    const float* w_dc2  = (const float*)d_in[10];
    const float* g2     = (const float*)d_in[11];
    const float* beta2  = (const float*)d_in[12];
    const float* m2     = (const float*)d_in[13];
    const float* v2     = (const float*)d_in[14];
    float* out = (float*)d_out;

    float *off1, *off2, *out1, *xt, *wt1, *wt2;
    cudaGetSymbolAddress((void**)&off1, g_off1);
    cudaGetSymbolAddress((void**)&off2, g_off2);
    cudaGetSymbolAddress((void**)&out1, g_out1);
    cudaGetSymbolAddress((void**)&xt,   g_xt);
    cudaGetSymbolAddress((void**)&wt1,  g_wt1);
    cudaGetSymbolAddress((void**)&wt2,  g_wt2);

    dim3 ocBlk(64, 6);
    dim3 trGrid(HW / 32, CC / 32, BB), trBlk(32, 8);

    wtrans_kernel<<<CIKK, CC>>>(w_dc1, w_dc2);

    // stage 1
    offconv_kernel<<<BB * HH, ocBlk>>>(x, w_off1, b_off1, off1);
    transpose_kernel<<<trGrid, trBlk>>>(x, xt);
    deform_kernel<<<BB * HW / DT, 64>>>(xt, off1, wt1, g1, beta1, m1, v1,
                                        nullptr, out1);
    // stage 2
    offconv_kernel<<<BB * HH, ocBlk>>>(out1, w_off2, b_off2, off2);
    transpose_kernel<<<trGrid, trBlk>>>(out1, xt);
    deform_kernel<<<BB * HW / DT, 64>>>(xt, off2, wt2, g2, beta2, m2, v2,
                                        x, out);
}